// round 8
// baseline (speedup 1.0000x reference)
#include <cuda_runtime.h>

// DecoderSphere: fully fused, 2 points per thread sharing weight LDS (halves
// the LSU load that bound R2), f32x2 packed fp32 math, cf kept in registers.
// Static smem only (43KB < 48KB) -> no cudaFuncSetAttribute, no static guards,
// fully graph-capture-safe.

#define BATCH 16
#define TPTS  65536
#define DIM   32
#define NPTS  (BATCH * TPTS)
#define TPB   128
#define HALF_PTS (NPTS / 2)

typedef unsigned long long ull;

__device__ __forceinline__ ull pack2(float lo, float hi) {
    ull r; asm("mov.b64 %0, {%1, %2};" : "=l"(r) : "f"(lo), "f"(hi)); return r;
}
__device__ __forceinline__ void unpack2(ull v, float &lo, float &hi) {
    asm("mov.b64 {%0, %1}, %2;" : "=f"(lo), "=f"(hi) : "l"(v));
}
__device__ __forceinline__ ull fma2(ull a, ull b, ull c) {
    ull r; asm("fma.rn.f32x2 %0, %1, %2, %3;" : "=l"(r) : "l"(a), "l"(b), "l"(c)); return r;
}
__device__ __forceinline__ ull add2(ull a, ull b) {
    ull r; asm("add.rn.f32x2 %0, %1, %2;" : "=l"(r) : "l"(a), "l"(b)); return r;
}
__device__ __forceinline__ ull mul2(ull a, ull b) {
    ull r; asm("mul.rn.f32x2 %0, %1, %2;" : "=l"(r) : "l"(a), "l"(b)); return r;
}

// Shared weight arena layout (floats) — 43008 bytes, fits static 48KB.
#define OFF_FCPW 0          // [3][32]
#define OFF_FCPB 96         // [32]
#define OFF_W0   128        // [5][32][32]
#define OFF_B0   5248       // [5][32]
#define OFF_W1   5408       // [5][32][32]
#define OFF_B1   10528      // [5][32]
#define OFF_FOW  10688      // [32]
#define OFF_FOB  10720      // [1]
#define S_TOTAL  10752

// Compute sphere bilinear cf for one point into 16 packed f32x2 regs.
__device__ __forceinline__ void interp_point(const float* __restrict__ c, int i,
                                             float px, float py, float pz,
                                             ull* __restrict__ cf)
{
    const float PI_F = 3.1415927410125732f;
    float lat = 90.0f - (atan2f(pz, sqrtf(px * px + py * py)) * 180.0f) / PI_F;
    float mer = fmodf(360.0f + (atan2f(py, px) * 180.0f) / PI_F, 360.0f);
    float y_grid = floorf(lat / 2.8125f);
    float x_grid = floorf(mer / 5.625f);

    float xlf = x_grid - 1.0f; xlf -= 64.0f * floorf(xlf * 0.015625f);
    float xrf = x_grid + 1.0f; xrf -= 64.0f * floorf(xrf * 0.015625f);
    float ylf = y_grid - 1.0f; ylf -= floorf(ylf * 0.015625f);
    float yhf = y_grid + 1.0f; yhf -= floorf(yhf * 0.015625f);

    const float dx = xrf - x_grid;
    const float dy = yhf - y_grid;
    const int xl = (int)xlf, xr = (int)xrf, yl = (int)ylf, yh = (int)yhf;
    const int bb = i >> 16;

    const float* gb = c + (size_t)bb * (64 * 64 * DIM);
    const float4* F11 = (const float4*)(gb + (size_t)(xl * 64 + yl) * DIM);
    const float4* F12 = (const float4*)(gb + (size_t)(xr * 64 + yl) * DIM);
    const float4* F21 = (const float4*)(gb + (size_t)(xl * 64 + yh) * DIM);
    const float4* F22 = (const float4*)(gb + (size_t)(xr * 64 + yh) * DIM);

    const float w11 = dx * dy, w12 = (1.0f - dx) * dy;
    const float w21 = dx * (1.0f - dy), w22 = (1.0f - dx) * (1.0f - dy);
    const ull W11 = pack2(w11, w11), W12 = pack2(w12, w12);
    const ull W21 = pack2(w21, w21), W22 = pack2(w22, w22);

    #pragma unroll
    for (int q = 0; q < 8; ++q) {
        float4 a  = F11[q];
        float4 b4 = F12[q];
        float4 c4 = F21[q];
        float4 d4 = F22[q];
        ull acc = mul2(pack2(a.x, a.y), W11);
        acc = fma2(pack2(b4.x, b4.y), W12, acc);
        acc = fma2(pack2(c4.x, c4.y), W21, acc);
        acc = fma2(pack2(d4.x, d4.y), W22, acc);
        cf[2 * q] = acc;
        acc = mul2(pack2(a.z, a.w), W11);
        acc = fma2(pack2(b4.z, b4.w), W12, acc);
        acc = fma2(pack2(c4.z, c4.w), W21, acc);
        acc = fma2(pack2(d4.z, d4.w), W22, acc);
        cf[2 * q + 1] = acc;
    }
}

__global__ void __launch_bounds__(TPB, 1)
decoder_sphere_kernel(const float* __restrict__ p,
                      const float* __restrict__ c,
                      const float* __restrict__ fcpw,
                      const float* __restrict__ fcpb,
                      const float* __restrict__ w0,
                      const float* __restrict__ b0,
                      const float* __restrict__ w1,
                      const float* __restrict__ b1,
                      const float* __restrict__ fow,
                      const float* __restrict__ fob,
                      float* __restrict__ out)
{
    __shared__ __align__(16) float s[S_TOTAL];

    const int tid = threadIdx.x;
    for (int idx = tid; idx < 96;   idx += TPB) s[OFF_FCPW + idx] = fcpw[idx];
    for (int idx = tid; idx < 32;   idx += TPB) s[OFF_FCPB + idx] = fcpb[idx];
    for (int idx = tid; idx < 5120; idx += TPB) s[OFF_W0   + idx] = w0[idx];
    for (int idx = tid; idx < 160;  idx += TPB) s[OFF_B0   + idx] = b0[idx];
    for (int idx = tid; idx < 5120; idx += TPB) s[OFF_W1   + idx] = w1[idx];
    for (int idx = tid; idx < 160;  idx += TPB) s[OFF_B1   + idx] = b1[idx];
    for (int idx = tid; idx < 32;   idx += TPB) s[OFF_FOW  + idx] = fow[idx];
    if (tid == 0) s[OFF_FOB] = fob[0];
    __syncthreads();

    const int iA = blockIdx.x * TPB + tid;
    const int iB = iA + HALF_PTS;

    const float* ppA = p + (size_t)iA * 3;
    const float pAx = ppA[0], pAy = ppA[1], pAz = ppA[2];
    const float* ppB = p + (size_t)iB * 3;
    const float pBx = ppB[0], pBy = ppB[1], pBz = ppB[2];

    ull cfA[16], cfB[16];
    interp_point(c, iA, pAx, pAy, pAz, cfA);
    interp_point(c, iB, pBx, pBy, pBz, cfB);

    // net = p @ fc_p_w + fc_p_b
    const ull PXa = pack2(pAx, pAx), PYa = pack2(pAy, pAy), PZa = pack2(pAz, pAz);
    const ull PXb = pack2(pBx, pBx), PYb = pack2(pBy, pBy), PZb = pack2(pBz, pBz);
    const ull* fpw0 = (const ull*)&s[OFF_FCPW + 0];
    const ull* fpw1 = (const ull*)&s[OFF_FCPW + 32];
    const ull* fpw2 = (const ull*)&s[OFF_FCPW + 64];
    const ull* fpb  = (const ull*)&s[OFF_FCPB];

    ull netA[16], netB[16];
    #pragma unroll
    for (int k = 0; k < 16; ++k) {
        ull wk0 = fpw0[k], wk1 = fpw1[k], wk2 = fpw2[k], bk = fpb[k];
        ull a = fma2(PXa, wk0, bk);
        a = fma2(PYa, wk1, a);
        netA[k] = fma2(PZa, wk2, a);
        ull bacc = fma2(PXb, wk0, bk);
        bacc = fma2(PYb, wk1, bacc);
        netB[k] = fma2(PZb, wk2, bacc);
    }

    #pragma unroll
    for (int l = 0; l < 5; ++l) {
        const float* W0 = &s[OFF_W0 + l * 1024];
        const float* W1 = &s[OFF_W1 + l * 1024];
        const ull* B0 = (const ull*)&s[OFF_B0 + l * 32];
        const ull* B1 = (const ull*)&s[OFF_B1 + l * 32];

        // net += cf
        #pragma unroll
        for (int k = 0; k < 16; ++k) {
            netA[k] = add2(netA[k], cfA[k]);
            netB[k] = add2(netB[k], cfB[k]);
        }

        // h = relu( relu(net) @ w0 + b0 ) ; one weight load feeds A and B
        ull hA[16], hB[16];
        #pragma unroll
        for (int k = 0; k < 16; ++k) { ull b = B0[k]; hA[k] = b; hB[k] = b; }

        #pragma unroll
        for (int k = 0; k < 16; ++k) {
            float a0, a1, b0v, b1v;
            unpack2(netA[k], a0, a1);
            unpack2(netB[k], b0v, b1v);
            a0 = fmaxf(a0, 0.0f); a1 = fmaxf(a1, 0.0f);
            b0v = fmaxf(b0v, 0.0f); b1v = fmaxf(b1v, 0.0f);
            const ull RLa = pack2(a0, a0), RHa = pack2(a1, a1);
            const ull RLb = pack2(b0v, b0v), RHb = pack2(b1v, b1v);
            const float4* r0 = (const float4*)&W0[(2 * k) * 32];
            const float4* r1 = (const float4*)&W0[(2 * k + 1) * 32];
            #pragma unroll
            for (int q = 0; q < 8; ++q) {
                float4 wa = r0[q];
                ull wl = pack2(wa.x, wa.y), wh = pack2(wa.z, wa.w);
                hA[2 * q]     = fma2(RLa, wl, hA[2 * q]);
                hA[2 * q + 1] = fma2(RLa, wh, hA[2 * q + 1]);
                hB[2 * q]     = fma2(RLb, wl, hB[2 * q]);
                hB[2 * q + 1] = fma2(RLb, wh, hB[2 * q + 1]);
            }
            #pragma unroll
            for (int q = 0; q < 8; ++q) {
                float4 wb = r1[q];
                ull wl = pack2(wb.x, wb.y), wh = pack2(wb.z, wb.w);
                hA[2 * q]     = fma2(RHa, wl, hA[2 * q]);
                hA[2 * q + 1] = fma2(RHa, wh, hA[2 * q + 1]);
                hB[2 * q]     = fma2(RHb, wl, hB[2 * q]);
                hB[2 * q + 1] = fma2(RHb, wh, hB[2 * q + 1]);
            }
        }

        // net = net + relu(h) @ w1 + b1
        #pragma unroll
        for (int k = 0; k < 16; ++k) {
            ull b = B1[k];
            netA[k] = add2(netA[k], b);
            netB[k] = add2(netB[k], b);
        }

        #pragma unroll
        for (int k = 0; k < 16; ++k) {
            float a0, a1, b0v, b1v;
            unpack2(hA[k], a0, a1);
            unpack2(hB[k], b0v, b1v);
            a0 = fmaxf(a0, 0.0f); a1 = fmaxf(a1, 0.0f);
            b0v = fmaxf(b0v, 0.0f); b1v = fmaxf(b1v, 0.0f);
            const ull RLa = pack2(a0, a0), RHa = pack2(a1, a1);
            const ull RLb = pack2(b0v, b0v), RHb = pack2(b1v, b1v);
            const float4* r0 = (const float4*)&W1[(2 * k) * 32];
            const float4* r1 = (const float4*)&W1[(2 * k + 1) * 32];
            #pragma unroll
            for (int q = 0; q < 8; ++q) {
                float4 wa = r0[q];
                ull wl = pack2(wa.x, wa.y), wh = pack2(wa.z, wa.w);
                netA[2 * q]     = fma2(RLa, wl, netA[2 * q]);
                netA[2 * q + 1] = fma2(RLa, wh, netA[2 * q + 1]);
                netB[2 * q]     = fma2(RLb, wl, netB[2 * q]);
                netB[2 * q + 1] = fma2(RLb, wh, netB[2 * q + 1]);
            }
            #pragma unroll
            for (int q = 0; q < 8; ++q) {
                float4 wb = r1[q];
                ull wl = pack2(wb.x, wb.y), wh = pack2(wb.z, wb.w);
                netA[2 * q]     = fma2(RHa, wl, netA[2 * q]);
                netA[2 * q + 1] = fma2(RHa, wh, netA[2 * q + 1]);
                netB[2 * q]     = fma2(RHb, wl, netB[2 * q]);
                netB[2 * q + 1] = fma2(RHb, wh, netB[2 * q + 1]);
            }
        }
    }

    // out = relu(net) @ fc_out_w + fc_out_b
    const float* FW = &s[OFF_FOW];
    float accA = s[OFF_FOB];
    float accB = accA;
    #pragma unroll
    for (int k = 0; k < 16; ++k) {
        float w0v = FW[2 * k], w1v = FW[2 * k + 1];
        float a0, a1, b0v, b1v;
        unpack2(netA[k], a0, a1);
        unpack2(netB[k], b0v, b1v);
        accA = fmaf(fmaxf(a0, 0.0f), w0v, accA);
        accA = fmaf(fmaxf(a1, 0.0f), w1v, accA);
        accB = fmaf(fmaxf(b0v, 0.0f), w0v, accB);
        accB = fmaf(fmaxf(b1v, 0.0f), w1v, accB);
    }
    out[iA] = accA;
    out[iB] = accB;
}

extern "C" void kernel_launch(void* const* d_in, const int* in_sizes, int n_in,
                              void* d_out, int out_size)
{
    const float* p    = (const float*)d_in[0];
    const float* c    = (const float*)d_in[2];
    const float* fcpw = (const float*)d_in[4];
    const float* fcpb = (const float*)d_in[5];
    const float* w0   = (const float*)d_in[6];
    const float* b0   = (const float*)d_in[7];
    const float* w1   = (const float*)d_in[8];
    const float* b1   = (const float*)d_in[9];
    const float* fow  = (const float*)d_in[10];
    const float* fob  = (const float*)d_in[11];
    float* out = (float*)d_out;

    decoder_sphere_kernel<<<HALF_PTS / TPB, TPB>>>(
        p, c, fcpw, fcpb, w0, b0, w1, b1, fow, fob, out);
}

// round 11
// speedup vs baseline: 2.6879x; 2.6879x over previous
#include <cuda_runtime.h>
#include <cuda_bf16.h>
#include <cstdint>

// DecoderSphere via warp-level bf16-3x mma.sync (m16n8k16), fragment-resident.
// Persistent: 296 CTAs x 128 thr (4 warps); warp = 32 points; CTA tile = 128 points.
// Each 32x32 GEMM: 2Mtile x 4Ntile x 2Ktile x 3products = 48 mma/warp.
// C-fragments of one layer ARE the A-fragments of the next (no shuffles).

#define TPB   128
#define NPTS  (16 * 65536)
#define NTILE (NPTS / 128)     // 8192
#define GRID  296

// ---- SMEM layout (bytes) ----
#define OFF_WFRAG 0                    // 20 matrices x 2048B (fragment-ordered bf16)
#define OFF_B0    40960                // 5*32 f32
#define OFF_B1    (OFF_B0 + 640)
#define OFF_FCPW  (OFF_B1 + 640)       // 96 f32
#define OFF_FCPB  (OFF_FCPW + 384)     // 32 f32
#define OFF_BUFCF (OFF_FCPB + 128)     // [128][34] f32
#define BUF_STRIDE 34
#define BUF_BYTES  (128 * BUF_STRIDE * 4)
#define OFF_BUFN0 (OFF_BUFCF + BUF_BYTES)
#define SMEM_BYTES (OFF_BUFN0 + BUF_BYTES)

// matrix id: (l*2 + which)*2 + half ; base byte offset in WFRAG
#define MAT_BASE(l, which, half) (OFF_WFRAG + ((((l) * 2 + (which)) * 2 + (half)) * 2048))

// pack two f32 -> bf16x2 (lo = a, hi = b)
static __device__ __forceinline__ uint32_t cvt2(float a, float b) {
    uint32_t r;
    asm("cvt.rn.bf16x2.f32 %0, %1, %2;" : "=r"(r) : "f"(b), "f"(a));
    return r;
}

static __device__ __forceinline__ void mma_bf16(float* c, uint32_t a0, uint32_t a1,
                                                uint32_t a2, uint32_t a3,
                                                uint32_t b0, uint32_t b1) {
    asm volatile(
        "mma.sync.aligned.m16n8k16.row.col.f32.bf16.bf16.f32 "
        "{%0,%1,%2,%3}, {%4,%5,%6,%7}, {%8,%9}, {%0,%1,%2,%3};"
        : "+f"(c[0]), "+f"(c[1]), "+f"(c[2]), "+f"(c[3])
        : "r"(a0), "r"(a1), "r"(a2), "r"(a3), "r"(b0), "r"(b1));
}

// one 32->32 GEMM on fragments: acc[m][nt][4] += split3(x) @ (Whi + Wlo)
static __device__ __forceinline__ void gemm_frag(const char* smem,
                                                 const float x[2][4][4],
                                                 float acc[2][4][4],
                                                 int mb_hi, int mb_lo, int lane)
{
    // build A-fragments (hi + residual lo) from C-layout x
    // A-reg order: a0=(row g, k-lo), a1=(row g+8, k-lo), a2=(row g, k-hi), a3=(row g+8, k-hi)
    // enumeration r = (ntoff<<1)|rowhalf maps IDENTITY onto a-index: ai = r
    uint32_t ah[2][2][4], al[2][2][4];
    #pragma unroll
    for (int m = 0; m < 2; ++m) {
        #pragma unroll
        for (int kt = 0; kt < 2; ++kt) {
            #pragma unroll
            for (int r = 0; r < 4; ++r) {
                const float v0 = x[m][2 * kt + (r >> 1)][(r & 1) * 2 + 0];
                const float v1 = x[m][2 * kt + (r >> 1)][(r & 1) * 2 + 1];
                uint32_t hp = cvt2(v0, v1);
                float r0 = v0 - __uint_as_float(hp << 16);
                float r1 = v1 - __uint_as_float(hp & 0xffff0000u);
                const int ai = r;   // FIX R11: was a bit-swap that exchanged a1<->a2
                ah[m][kt][ai] = hp;
                al[m][kt][ai] = cvt2(r0, r1);
            }
        }
    }

    #pragma unroll
    for (int kt = 0; kt < 2; ++kt) {
        #pragma unroll
        for (int nt = 0; nt < 4; ++nt) {
            const int slot = ((kt * 4 + nt) * 32 + lane) * 8;
            uint2 bh = *(const uint2*)(smem + mb_hi + slot);
            uint2 bl = *(const uint2*)(smem + mb_lo + slot);
            #pragma unroll
            for (int m = 0; m < 2; ++m) {
                mma_bf16(acc[m][nt], ah[m][kt][0], ah[m][kt][1], ah[m][kt][2], ah[m][kt][3], bh.x, bh.y);
                mma_bf16(acc[m][nt], ah[m][kt][0], ah[m][kt][1], ah[m][kt][2], ah[m][kt][3], bl.x, bl.y);
                mma_bf16(acc[m][nt], al[m][kt][0], al[m][kt][1], al[m][kt][2], al[m][kt][3], bh.x, bh.y);
            }
        }
    }
}

__global__ void __launch_bounds__(TPB, 2)
decoder_sphere_mma(const float* __restrict__ p,
                   const float* __restrict__ c,
                   const float* __restrict__ fcpw,
                   const float* __restrict__ fcpb,
                   const float* __restrict__ w0g,
                   const float* __restrict__ b0g,
                   const float* __restrict__ w1g,
                   const float* __restrict__ b1g,
                   const float* __restrict__ fowg,
                   const float* __restrict__ fobg,
                   float* __restrict__ out)
{
    extern __shared__ __align__(16) char smem[];
    float* sf = (float*)smem;
    const int tid  = threadIdx.x;
    const int wid  = tid >> 5;
    const int lane = tid & 31;
    const int g    = lane >> 2;
    const int tig  = lane & 3;

    // ---- stage scalars ----
    for (int i = tid; i < 160; i += TPB) {
        *(float*)(smem + OFF_B0 + i * 4) = b0g[i];
        *(float*)(smem + OFF_B1 + i * 4) = b1g[i];
    }
    for (int i = tid; i < 96; i += TPB) *(float*)(smem + OFF_FCPW + i * 4) = fcpw[i];
    for (int i = tid; i < 32; i += TPB) *(float*)(smem + OFF_FCPB + i * 4) = fcpb[i];

    // ---- stage weights into fragment-ordered bf16 hi/lo arrays ----
    for (int idx = tid; idx < 5120; idx += TPB) {
        int l = idx >> 10;
        int r = idx & 1023;
        int k = r >> 5;     // input feature (K)
        int n = r & 31;     // output feature (N)
        int kt = k >> 4, kr = k & 15;
        int hb = kr >> 3, ktig = (kr >> 1) & 3, j = kr & 1;
        int gg = n & 7, nt = n >> 3;
        int ln = (gg << 2) | ktig;
        int off = ((((kt << 2) | nt) << 5) + ln) * 4 + (hb << 1) + j;  // in bf16 units

        float v0 = w0g[idx];
        __nv_bfloat16 h0 = __float2bfloat16_rn(v0);
        __nv_bfloat16 l0 = __float2bfloat16_rn(v0 - __bfloat162float(h0));
        *(__nv_bfloat16*)(smem + MAT_BASE(l, 0, 0) + off * 2) = h0;
        *(__nv_bfloat16*)(smem + MAT_BASE(l, 0, 1) + off * 2) = l0;

        float v1 = w1g[idx];
        __nv_bfloat16 h1 = __float2bfloat16_rn(v1);
        __nv_bfloat16 l1 = __float2bfloat16_rn(v1 - __bfloat162float(h1));
        *(__nv_bfloat16*)(smem + MAT_BASE(l, 1, 0) + off * 2) = h1;
        *(__nv_bfloat16*)(smem + MAT_BASE(l, 1, 1) + off * 2) = l1;
    }

    // fow fragment + fob in regs (loaded once)
    float fwreg[8];
    #pragma unroll
    for (int nt = 0; nt < 4; ++nt) {
        fwreg[2 * nt]     = fowg[8 * nt + 2 * tig];
        fwreg[2 * nt + 1] = fowg[8 * nt + 2 * tig + 1];
    }
    const float fob = fobg[0];
    __syncthreads();

    // ---- persistent tile loop ----
    for (int t = blockIdx.x; t < NTILE; t += GRID) {
        const int tbase = t << 7;
        const int i = tbase + tid;
        const int bb = i >> 16;

        // ---- per-point: sphere interp + net0, write to smem buffers ----
        {
            const float* pp = p + (size_t)i * 3;
            const float px = pp[0], py = pp[1], pz = pp[2];
            const float PI_F = 3.1415927410125732f;
            float lat = 90.0f - (atan2f(pz, sqrtf(px * px + py * py)) * 180.0f) / PI_F;
            float mer = fmodf(360.0f + (atan2f(py, px) * 180.0f) / PI_F, 360.0f);
            float y_grid = floorf(lat / 2.8125f);
            float x_grid = floorf(mer / 5.625f);
            float xlf = x_grid - 1.0f; xlf -= 64.0f * floorf(xlf * 0.015625f);
            float xrf = x_grid + 1.0f; xrf -= 64.0f * floorf(xrf * 0.015625f);
            float ylf = y_grid - 1.0f; ylf -= floorf(ylf * 0.015625f);
            float yhf = y_grid + 1.0f; yhf -= floorf(yhf * 0.015625f);
            const float dx = xrf - x_grid;
            const float dy = yhf - y_grid;
            const int xl = (int)xlf, xr = (int)xrf, yl = (int)ylf, yh = (int)yhf;

            const float* gb = c + (size_t)bb * (64 * 64 * 32);
            const float4* F11 = (const float4*)(gb + (size_t)(xl * 64 + yl) * 32);
            const float4* F12 = (const float4*)(gb + (size_t)(xr * 64 + yl) * 32);
            const float4* F21 = (const float4*)(gb + (size_t)(xl * 64 + yh) * 32);
            const float4* F22 = (const float4*)(gb + (size_t)(xr * 64 + yh) * 32);
            const float w11 = dx * dy, w12 = (1.0f - dx) * dy;
            const float w21 = dx * (1.0f - dy), w22 = (1.0f - dx) * (1.0f - dy);

            float2* rowc = (float2*)(smem + OFF_BUFCF + (size_t)tid * BUF_STRIDE * 4);
            float2* rown = (float2*)(smem + OFF_BUFN0 + (size_t)tid * BUF_STRIDE * 4);
            #pragma unroll
            for (int q = 0; q < 8; ++q) {
                float4 a = F11[q], b4 = F12[q], c4 = F21[q], d4 = F22[q];
                float cf0 = a.x * w11 + b4.x * w12 + c4.x * w21 + d4.x * w22;
                float cf1 = a.y * w11 + b4.y * w12 + c4.y * w21 + d4.y * w22;
                float cf2 = a.z * w11 + b4.z * w12 + c4.z * w21 + d4.z * w22;
                float cf3 = a.w * w11 + b4.w * w12 + c4.w * w21 + d4.w * w22;
                rowc[2 * q]     = make_float2(cf0, cf1);
                rowc[2 * q + 1] = make_float2(cf2, cf3);
                int f = 4 * q;
                float n0 = px * sf[OFF_FCPW / 4 + f]     + py * sf[OFF_FCPW / 4 + 32 + f]     + pz * sf[OFF_FCPW / 4 + 64 + f]     + sf[OFF_FCPB / 4 + f];
                float n1 = px * sf[OFF_FCPW / 4 + f + 1] + py * sf[OFF_FCPW / 4 + 33 + f]     + pz * sf[OFF_FCPW / 4 + 65 + f]     + sf[OFF_FCPB / 4 + f + 1];
                float n2 = px * sf[OFF_FCPW / 4 + f + 2] + py * sf[OFF_FCPW / 4 + 34 + f]     + pz * sf[OFF_FCPW / 4 + 66 + f]     + sf[OFF_FCPB / 4 + f + 2];
                float n3 = px * sf[OFF_FCPW / 4 + f + 3] + py * sf[OFF_FCPW / 4 + 35 + f]     + pz * sf[OFF_FCPW / 4 + 67 + f]     + sf[OFF_FCPB / 4 + f + 3];
                rown[2 * q]     = make_float2(n0, n1);
                rown[2 * q + 1] = make_float2(n2, n3);
            }
        }
        __syncthreads();

        // ---- load fragments: net (from net0) and cf ----
        float net[2][4][4], cf[2][4][4];
        #pragma unroll
        for (int m = 0; m < 2; ++m) {
            const int rlo = 32 * wid + g + 16 * m;
            const int rhi = rlo + 8;
            #pragma unroll
            for (int nt = 0; nt < 4; ++nt) {
                const int cidx = 8 * nt + 2 * tig;
                float2 nl = *(float2*)(smem + OFF_BUFN0 + (rlo * BUF_STRIDE + cidx) * 4);
                float2 nh = *(float2*)(smem + OFF_BUFN0 + (rhi * BUF_STRIDE + cidx) * 4);
                net[m][nt][0] = nl.x; net[m][nt][1] = nl.y;
                net[m][nt][2] = nh.x; net[m][nt][3] = nh.y;
                float2 cl = *(float2*)(smem + OFF_BUFCF + (rlo * BUF_STRIDE + cidx) * 4);
                float2 ch = *(float2*)(smem + OFF_BUFCF + (rhi * BUF_STRIDE + cidx) * 4);
                cf[m][nt][0] = cl.x; cf[m][nt][1] = cl.y;
                cf[m][nt][2] = ch.x; cf[m][nt][3] = ch.y;
            }
        }
        __syncthreads();   // buffers free for next tile

        // ---- 5 resnet blocks, fully fragment-resident ----
        #pragma unroll 1
        for (int l = 0; l < 5; ++l) {
            float xr[2][4][4], h[2][4][4];
            #pragma unroll
            for (int m = 0; m < 2; ++m)
                #pragma unroll
                for (int nt = 0; nt < 4; ++nt)
                    #pragma unroll
                    for (int j = 0; j < 4; ++j) {
                        net[m][nt][j] += cf[m][nt][j];
                        xr[m][nt][j] = fmaxf(net[m][nt][j], 0.0f);
                    }

            // h = relu(x) @ W0 + b0
            #pragma unroll
            for (int nt = 0; nt < 4; ++nt) {
                float2 bp = *(float2*)(smem + OFF_B0 + (l * 32 + 8 * nt + 2 * tig) * 4);
                h[0][nt][0] = bp.x; h[0][nt][1] = bp.y; h[0][nt][2] = bp.x; h[0][nt][3] = bp.y;
                h[1][nt][0] = bp.x; h[1][nt][1] = bp.y; h[1][nt][2] = bp.x; h[1][nt][3] = bp.y;
            }
            gemm_frag(smem, xr, h, MAT_BASE(l, 0, 0), MAT_BASE(l, 0, 1), lane);

            // net += relu(h) @ W1 + b1
            float d[2][4][4];
            #pragma unroll
            for (int m = 0; m < 2; ++m)
                #pragma unroll
                for (int nt = 0; nt < 4; ++nt)
                    #pragma unroll
                    for (int j = 0; j < 4; ++j)
                        xr[m][nt][j] = fmaxf(h[m][nt][j], 0.0f);
            #pragma unroll
            for (int nt = 0; nt < 4; ++nt) {
                float2 bp = *(float2*)(smem + OFF_B1 + (l * 32 + 8 * nt + 2 * tig) * 4);
                d[0][nt][0] = bp.x; d[0][nt][1] = bp.y; d[0][nt][2] = bp.x; d[0][nt][3] = bp.y;
                d[1][nt][0] = bp.x; d[1][nt][1] = bp.y; d[1][nt][2] = bp.x; d[1][nt][3] = bp.y;
            }
            gemm_frag(smem, xr, d, MAT_BASE(l, 1, 0), MAT_BASE(l, 1, 1), lane);

            #pragma unroll
            for (int m = 0; m < 2; ++m)
                #pragma unroll
                for (int nt = 0; nt < 4; ++nt)
                    #pragma unroll
                    for (int j = 0; j < 4; ++j)
                        net[m][nt][j] += d[m][nt][j];
        }

        // ---- head: out = relu(net) . fow + fob ; reduce across 4-lane group ----
        float pr0 = 0.f, pr1 = 0.f, pr2 = 0.f, pr3 = 0.f;
        #pragma unroll
        for (int nt = 0; nt < 4; ++nt) {
            pr0 += fmaxf(net[0][nt][0], 0.f) * fwreg[2 * nt] + fmaxf(net[0][nt][1], 0.f) * fwreg[2 * nt + 1];
            pr1 += fmaxf(net[0][nt][2], 0.f) * fwreg[2 * nt] + fmaxf(net[0][nt][3], 0.f) * fwreg[2 * nt + 1];
            pr2 += fmaxf(net[1][nt][0], 0.f) * fwreg[2 * nt] + fmaxf(net[1][nt][1], 0.f) * fwreg[2 * nt + 1];
            pr3 += fmaxf(net[1][nt][2], 0.f) * fwreg[2 * nt] + fmaxf(net[1][nt][3], 0.f) * fwreg[2 * nt + 1];
        }
        #pragma unroll
        for (int s = 1; s <= 2; s <<= 1) {
            pr0 += __shfl_xor_sync(0xffffffffu, pr0, s);
            pr1 += __shfl_xor_sync(0xffffffffu, pr1, s);
            pr2 += __shfl_xor_sync(0xffffffffu, pr2, s);
            pr3 += __shfl_xor_sync(0xffffffffu, pr3, s);
        }
        if (tig == 0) {
            const int base = tbase + 32 * wid + g;
            out[base]      = pr0 + fob;
            out[base + 8]  = pr1 + fob;
            out[base + 16] = pr2 + fob;
            out[base + 24] = pr3 + fob;
        }
    }
}

extern "C" void kernel_launch(void* const* d_in, const int* in_sizes, int n_in,
                              void* d_out, int out_size)
{
    const float* p    = (const float*)d_in[0];
    const float* c    = (const float*)d_in[2];
    const float* fcpw = (const float*)d_in[4];
    const float* fcpb = (const float*)d_in[5];
    const float* w0   = (const float*)d_in[6];
    const float* b0   = (const float*)d_in[7];
    const float* w1   = (const float*)d_in[8];
    const float* b1   = (const float*)d_in[9];
    const float* fow  = (const float*)d_in[10];
    const float* fob  = (const float*)d_in[11];
    float* out = (float*)d_out;

    cudaFuncSetAttribute(decoder_sphere_mma,
                         cudaFuncAttributeMaxDynamicSharedMemorySize, SMEM_BYTES);
    decoder_sphere_mma<<<GRID, TPB, SMEM_BYTES>>>(
        p, c, fcpw, fcpb, w0, b0, w1, b1, fow, fob, out);
}

// round 15
// speedup vs baseline: 3.4315x; 1.2766x over previous
#include <cuda_runtime.h>
#include <cuda_bf16.h>
#include <cstdint>

// DecoderSphere via warp-level bf16-3x mma.sync (m16n8k16), fragment-resident.
// R15 = R12 with BUF_STRIDE 34 -> 36 (float4 rows must be 16B aligned; 136B
// row pitch faulted). Cooperative coalesced gather, hi/lo weight interleave
// (LDS.128), net0 computed in fragment layout, 3 CTAs/SM.

#define TPB   128
#define NPTS  (16 * 65536)
#define NTILE (NPTS / 128)     // 8192
#define GRID  444              // 3 CTAs/SM

// ---- SMEM layout (bytes) ----
#define OFF_WFRAG 0                     // 10 matrices x 4096B (hi/lo interleaved 16B slots)
#define OFF_B0    40960                 // 5*32 f32
#define OFF_B1    (OFF_B0 + 640)
#define OFF_FCPW  (OFF_B1 + 640)        // 96 f32
#define OFF_FCPB  (OFF_FCPW + 384)      // 32 f32
#define OFF_EX    (OFF_FCPB + 128)      // 128 x 48B : {int4 offs, float4 w, float4 p}
#define EX_STRIDE 48
#define OFF_BUFCF (OFF_EX + 128 * EX_STRIDE)   // [128][36] f32 (144B row pitch, 16B aligned)
#define BUF_STRIDE 36
#define SMEM_BYTES (OFF_BUFCF + 128 * BUF_STRIDE * 4)   // 67328

// matrix (l,which) base: 4096B each, 16B slot = [bh.x bh.y bl.x bl.y]
#define MAT_BASE2(l, which) (OFF_WFRAG + (((l) * 2 + (which)) * 4096))

static __device__ __forceinline__ uint32_t cvt2(float a, float b) {
    uint32_t r;
    asm("cvt.rn.bf16x2.f32 %0, %1, %2;" : "=r"(r) : "f"(b), "f"(a));
    return r;
}

static __device__ __forceinline__ void mma_bf16(float* c, uint32_t a0, uint32_t a1,
                                                uint32_t a2, uint32_t a3,
                                                uint32_t b0, uint32_t b1) {
    asm volatile(
        "mma.sync.aligned.m16n8k16.row.col.f32.bf16.bf16.f32 "
        "{%0,%1,%2,%3}, {%4,%5,%6,%7}, {%8,%9}, {%0,%1,%2,%3};"
        : "+f"(c[0]), "+f"(c[1]), "+f"(c[2]), "+f"(c[3])
        : "r"(a0), "r"(a1), "r"(a2), "r"(a3), "r"(b0), "r"(b1));
}

// one 32->32 GEMM on fragments: acc += split3(x) @ (Whi + Wlo)
static __device__ __forceinline__ void gemm_frag(const char* smem,
                                                 const float x[2][4][4],
                                                 float acc[2][4][4],
                                                 int mbase, int lane)
{
    uint32_t ah[2][2][4], al[2][2][4];
    #pragma unroll
    for (int m = 0; m < 2; ++m) {
        #pragma unroll
        for (int kt = 0; kt < 2; ++kt) {
            #pragma unroll
            for (int r = 0; r < 4; ++r) {
                const float v0 = x[m][2 * kt + (r >> 1)][(r & 1) * 2 + 0];
                const float v1 = x[m][2 * kt + (r >> 1)][(r & 1) * 2 + 1];
                uint32_t hp = cvt2(v0, v1);
                float r0 = v0 - __uint_as_float(hp << 16);
                float r1 = v1 - __uint_as_float(hp & 0xffff0000u);
                ah[m][kt][r] = hp;
                al[m][kt][r] = cvt2(r0, r1);
            }
        }
    }

    #pragma unroll
    for (int kt = 0; kt < 2; ++kt) {
        #pragma unroll
        for (int nt = 0; nt < 4; ++nt) {
            const int slot = ((kt * 4 + nt) * 32 + lane) * 16;
            uint4 v = *(const uint4*)(smem + mbase + slot);
            #pragma unroll
            for (int m = 0; m < 2; ++m) {
                mma_bf16(acc[m][nt], ah[m][kt][0], ah[m][kt][1], ah[m][kt][2], ah[m][kt][3], v.x, v.y);
                mma_bf16(acc[m][nt], ah[m][kt][0], ah[m][kt][1], ah[m][kt][2], ah[m][kt][3], v.z, v.w);
                mma_bf16(acc[m][nt], al[m][kt][0], al[m][kt][1], al[m][kt][2], al[m][kt][3], v.x, v.y);
            }
        }
    }
}

__global__ void __launch_bounds__(TPB, 3)
decoder_sphere_mma(const float* __restrict__ p,
                   const float* __restrict__ c,
                   const float* __restrict__ fcpw,
                   const float* __restrict__ fcpb,
                   const float* __restrict__ w0g,
                   const float* __restrict__ b0g,
                   const float* __restrict__ w1g,
                   const float* __restrict__ b1g,
                   const float* __restrict__ fowg,
                   const float* __restrict__ fobg,
                   float* __restrict__ out)
{
    extern __shared__ __align__(16) char smem[];
    const int tid  = threadIdx.x;
    const int wid  = tid >> 5;
    const int lane = tid & 31;
    const int g    = lane >> 2;
    const int tig  = lane & 3;

    // ---- stage scalars ----
    for (int i = tid; i < 160; i += TPB) {
        *(float*)(smem + OFF_B0 + i * 4) = b0g[i];
        *(float*)(smem + OFF_B1 + i * 4) = b1g[i];
    }
    for (int i = tid; i < 96; i += TPB) *(float*)(smem + OFF_FCPW + i * 4) = fcpw[i];
    for (int i = tid; i < 32; i += TPB) *(float*)(smem + OFF_FCPB + i * 4) = fcpb[i];

    // ---- stage weights: fragment-ordered, hi/lo interleaved per 16B slot ----
    for (int idx = tid; idx < 5120; idx += TPB) {
        int l = idx >> 10;
        int r = idx & 1023;
        int k = r >> 5;     // input feature (K)
        int n = r & 31;     // output feature (N)
        int kt = k >> 4, kr = k & 15;
        int hb = kr >> 3, ktig = (kr >> 1) & 3, j = kr & 1;
        int gg = n & 7, nt = n >> 3;
        int ln = (gg << 2) | ktig;
        int slot = (((kt << 2) | nt) << 5) + ln;
        int bhi = slot * 16 + hb * 4 + j * 2;   // hi bf16 byte offset
        int blo = bhi + 8;                       // lo bf16 byte offset

        float v0 = w0g[idx];
        __nv_bfloat16 h0 = __float2bfloat16_rn(v0);
        __nv_bfloat16 l0 = __float2bfloat16_rn(v0 - __bfloat162float(h0));
        *(__nv_bfloat16*)(smem + MAT_BASE2(l, 0) + bhi) = h0;
        *(__nv_bfloat16*)(smem + MAT_BASE2(l, 0) + blo) = l0;

        float v1 = w1g[idx];
        __nv_bfloat16 h1 = __float2bfloat16_rn(v1);
        __nv_bfloat16 l1 = __float2bfloat16_rn(v1 - __bfloat162float(h1));
        *(__nv_bfloat16*)(smem + MAT_BASE2(l, 1) + bhi) = h1;
        *(__nv_bfloat16*)(smem + MAT_BASE2(l, 1) + blo) = l1;
    }

    // head weights (per-thread fragment) + bias
    float fwreg[8];
    #pragma unroll
    for (int nt = 0; nt < 4; ++nt) {
        fwreg[2 * nt]     = fowg[8 * nt + 2 * tig];
        fwreg[2 * nt + 1] = fowg[8 * nt + 2 * tig + 1];
    }
    const float fob = fobg[0];
    __syncthreads();

    // ---- persistent tile loop ----
    for (int t = blockIdx.x; t < NTILE; t += GRID) {
        const int tbase = t << 7;
        const int bb = tbase >> 16;              // batch constant per tile
        const int i = tbase + tid;

        // ---- phase 1: per-point indices/weights/p -> exchange ----
        {
            const float* pp = p + (size_t)i * 3;
            const float px = pp[0], py = pp[1], pz = pp[2];
            const float PI_F = 3.1415927410125732f;
            float lat = 90.0f - (atan2f(pz, sqrtf(px * px + py * py)) * 180.0f) / PI_F;
            float mer = fmodf(360.0f + (atan2f(py, px) * 180.0f) / PI_F, 360.0f);
            float y_grid = floorf(lat / 2.8125f);
            float x_grid = floorf(mer / 5.625f);
            float xlf = x_grid - 1.0f; xlf -= 64.0f * floorf(xlf * 0.015625f);
            float xrf = x_grid + 1.0f; xrf -= 64.0f * floorf(xrf * 0.015625f);
            float ylf = y_grid - 1.0f; ylf -= floorf(ylf * 0.015625f);
            float yhf = y_grid + 1.0f; yhf -= floorf(yhf * 0.015625f);
            const float dx = xrf - x_grid;
            const float dy = yhf - y_grid;
            const int xl = (int)xlf, xr = (int)xrf, yl = (int)ylf, yh = (int)yhf;

            char* ex = smem + OFF_EX + tid * EX_STRIDE;
            *(int4*)(ex) = make_int4((xl * 64 + yl) * 32, (xr * 64 + yl) * 32,
                                     (xl * 64 + yh) * 32, (xr * 64 + yh) * 32);
            *(float4*)(ex + 16) = make_float4(dx * dy, (1.0f - dx) * dy,
                                              dx * (1.0f - dy), (1.0f - dx) * (1.0f - dy));
            *(float4*)(ex + 32) = make_float4(px, py, pz, 0.0f);
        }
        __syncthreads();

        // ---- phase 2: cooperative coalesced gather -> BUFCF[point][col] ----
        {
            const float* gbase = c + (size_t)bb * (64 * 64 * 32);
            const int sub = lane >> 3, piece = lane & 7;
            #pragma unroll
            for (int grp = 0; grp < 8; ++grp) {
                const int lp = 32 * wid + grp * 4 + sub;       // CTA-local point
                const char* ex = smem + OFF_EX + lp * EX_STRIDE;
                const int4 offs = *(const int4*)(ex);
                const float4 ws = *(const float4*)(ex + 16);
                float4 a  = *(const float4*)(gbase + offs.x + piece * 4);
                float4 b4 = *(const float4*)(gbase + offs.y + piece * 4);
                float4 c4 = *(const float4*)(gbase + offs.z + piece * 4);
                float4 d4 = *(const float4*)(gbase + offs.w + piece * 4);
                float4 acc;
                acc.x = a.x * ws.x + b4.x * ws.y + c4.x * ws.z + d4.x * ws.w;
                acc.y = a.y * ws.x + b4.y * ws.y + c4.y * ws.z + d4.y * ws.w;
                acc.z = a.z * ws.x + b4.z * ws.y + c4.z * ws.z + d4.z * ws.w;
                acc.w = a.w * ws.x + b4.w * ws.y + c4.w * ws.z + d4.w * ws.w;
                *(float4*)(smem + OFF_BUFCF + (lp * BUF_STRIDE + piece * 4) * 4) = acc;
            }
        }
        __syncthreads();

        // ---- phase 3: load cf fragments; compute net0 in fragment layout ----
        float net[2][4][4], cf[2][4][4];
        {
            float4 prow[2][2];
            #pragma unroll
            for (int m = 0; m < 2; ++m)
                #pragma unroll
                for (int rh = 0; rh < 2; ++rh) {
                    const int row = 32 * wid + g + 16 * m + 8 * rh;
                    prow[m][rh] = *(const float4*)(smem + OFF_EX + row * EX_STRIDE + 32);
                }
            #pragma unroll
            for (int nt = 0; nt < 4; ++nt) {
                const int col = 8 * nt + 2 * tig;
                float2 f0 = *(const float2*)(smem + OFF_FCPW + col * 4);
                float2 f1 = *(const float2*)(smem + OFF_FCPW + (32 + col) * 4);
                float2 f2 = *(const float2*)(smem + OFF_FCPW + (64 + col) * 4);
                float2 fb = *(const float2*)(smem + OFF_FCPB + col * 4);
                #pragma unroll
                for (int m = 0; m < 2; ++m) {
                    #pragma unroll
                    for (int rh = 0; rh < 2; ++rh) {
                        float4 pv = prow[m][rh];
                        net[m][nt][2 * rh]     = pv.x * f0.x + pv.y * f1.x + pv.z * f2.x + fb.x;
                        net[m][nt][2 * rh + 1] = pv.x * f0.y + pv.y * f1.y + pv.z * f2.y + fb.y;
                    }
                    const int rlo = 32 * wid + g + 16 * m;
                    float2 cl = *(const float2*)(smem + OFF_BUFCF + (rlo * BUF_STRIDE + col) * 4);
                    float2 ch = *(const float2*)(smem + OFF_BUFCF + ((rlo + 8) * BUF_STRIDE + col) * 4);
                    cf[m][nt][0] = cl.x; cf[m][nt][1] = cl.y;
                    cf[m][nt][2] = ch.x; cf[m][nt][3] = ch.y;
                }
            }
        }
        __syncthreads();   // buffers free for next tile

        // ---- 5 resnet blocks, fragment-resident ----
        #pragma unroll 1
        for (int l = 0; l < 5; ++l) {
            float xr[2][4][4], h[2][4][4];
            #pragma unroll
            for (int m = 0; m < 2; ++m)
                #pragma unroll
                for (int nt = 0; nt < 4; ++nt)
                    #pragma unroll
                    for (int j = 0; j < 4; ++j) {
                        net[m][nt][j] += cf[m][nt][j];
                        xr[m][nt][j] = fmaxf(net[m][nt][j], 0.0f);
                    }

            #pragma unroll
            for (int nt = 0; nt < 4; ++nt) {
                float2 bp = *(const float2*)(smem + OFF_B0 + (l * 32 + 8 * nt + 2 * tig) * 4);
                h[0][nt][0] = bp.x; h[0][nt][1] = bp.y; h[0][nt][2] = bp.x; h[0][nt][3] = bp.y;
                h[1][nt][0] = bp.x; h[1][nt][1] = bp.y; h[1][nt][2] = bp.x; h[1][nt][3] = bp.y;
            }
            gemm_frag(smem, xr, h, MAT_BASE2(l, 0), lane);

            float d[2][4][4];
            #pragma unroll
            for (int m = 0; m < 2; ++m)
                #pragma unroll
                for (int nt = 0; nt < 4; ++nt)
                    #pragma unroll
                    for (int j = 0; j < 4; ++j)
                        xr[m][nt][j] = fmaxf(h[m][nt][j], 0.0f);
            #pragma unroll
            for (int nt = 0; nt < 4; ++nt) {
                float2 bp = *(const float2*)(smem + OFF_B1 + (l * 32 + 8 * nt + 2 * tig) * 4);
                d[0][nt][0] = bp.x; d[0][nt][1] = bp.y; d[0][nt][2] = bp.x; d[0][nt][3] = bp.y;
                d[1][nt][0] = bp.x; d[1][nt][1] = bp.y; d[1][nt][2] = bp.x; d[1][nt][3] = bp.y;
            }
            gemm_frag(smem, xr, d, MAT_BASE2(l, 1), lane);

            #pragma unroll
            for (int m = 0; m < 2; ++m)
                #pragma unroll
                for (int nt = 0; nt < 4; ++nt)
                    #pragma unroll
                    for (int j = 0; j < 4; ++j)
                        net[m][nt][j] += d[m][nt][j];
        }

        // ---- head + quad reduction ----
        float pr0 = 0.f, pr1 = 0.f, pr2 = 0.f, pr3 = 0.f;
        #pragma unroll
        for (int nt = 0; nt < 4; ++nt) {
            pr0 += fmaxf(net[0][nt][0], 0.f) * fwreg[2 * nt] + fmaxf(net[0][nt][1], 0.f) * fwreg[2 * nt + 1];
            pr1 += fmaxf(net[0][nt][2], 0.f) * fwreg[2 * nt] + fmaxf(net[0][nt][3], 0.f) * fwreg[2 * nt + 1];
            pr2 += fmaxf(net[1][nt][0], 0.f) * fwreg[2 * nt] + fmaxf(net[1][nt][1], 0.f) * fwreg[2 * nt + 1];
            pr3 += fmaxf(net[1][nt][2], 0.f) * fwreg[2 * nt] + fmaxf(net[1][nt][3], 0.f) * fwreg[2 * nt + 1];
        }
        #pragma unroll
        for (int s = 1; s <= 2; s <<= 1) {
            pr0 += __shfl_xor_sync(0xffffffffu, pr0, s);
            pr1 += __shfl_xor_sync(0xffffffffu, pr1, s);
            pr2 += __shfl_xor_sync(0xffffffffu, pr2, s);
            pr3 += __shfl_xor_sync(0xffffffffu, pr3, s);
        }
        if (tig == 0) {
            const int base = tbase + 32 * wid + g;
            out[base]      = pr0 + fob;
            out[base + 8]  = pr1 + fob;
            out[base + 16] = pr2 + fob;
            out[base + 24] = pr3 + fob;
        }
    }
}

extern "C" void kernel_launch(void* const* d_in, const int* in_sizes, int n_in,
                              void* d_out, int out_size)
{
    const float* p    = (const float*)d_in[0];
    const float* c    = (const float*)d_in[2];
    const float* fcpw = (const float*)d_in[4];
    const float* fcpb = (const float*)d_in[5];
    const float* w0   = (const float*)d_in[6];
    const float* b0   = (const float*)d_in[7];
    const float* w1   = (const float*)d_in[8];
    const float* b1   = (const float*)d_in[9];
    const float* fow  = (const float*)d_in[10];
    const float* fob  = (const float*)d_in[11];
    float* out = (float*)d_out;

    cudaFuncSetAttribute(decoder_sphere_mma,
                         cudaFuncAttributeMaxDynamicSharedMemorySize, SMEM_BYTES);
    decoder_sphere_mma<<<GRID, TPB, SMEM_BYTES>>>(
        p, c, fcpw, fcpb, w0, b0, w1, b1, fow, fob, out);
}

// round 16
// speedup vs baseline: 4.6248x; 1.3478x over previous
#include <cuda_runtime.h>
#include <cuda_fp16.h>
#include <cstdint>

// DecoderSphere via warp-level fp16 mma.sync (m16n8k16), fragment-resident.
// R16: A single fp16 (no runtime split), W split fp16 hi+lo -> 2 mma products
// per (kt,nt,m) instead of bf16-3x's 3. Cooperative coalesced gather,
// hi/lo weight interleave (LDS.128), net0 in fragment layout, 3 CTAs/SM.

#define TPB   128
#define NPTS  (16 * 65536)
#define NTILE (NPTS / 128)     // 8192
#define GRID  444              // 3 CTAs/SM

// ---- SMEM layout (bytes) ----
#define OFF_WFRAG 0                     // 10 matrices x 4096B (hi/lo interleaved 16B slots)
#define OFF_B0    40960                 // 5*32 f32
#define OFF_B1    (OFF_B0 + 640)
#define OFF_FCPW  (OFF_B1 + 640)        // 96 f32
#define OFF_FCPB  (OFF_FCPW + 384)      // 32 f32
#define OFF_EX    (OFF_FCPB + 128)      // 128 x 48B : {int4 offs, float4 w, float4 p}
#define EX_STRIDE 48
#define OFF_BUFCF (OFF_EX + 128 * EX_STRIDE)   // [128][36] f32 (144B pitch, 16B aligned)
#define BUF_STRIDE 36
#define SMEM_BYTES (OFF_BUFCF + 128 * BUF_STRIDE * 4)   // 67328

// matrix (l,which) base: 4096B each, 16B slot = [Wh 8B | Wl 8B]
#define MAT_BASE2(l, which) (OFF_WFRAG + (((l) * 2 + (which)) * 4096))

// pack two f32 -> f16x2 (lo = a, hi = b)
static __device__ __forceinline__ uint32_t cvt2h(float a, float b) {
    uint32_t r;
    asm("cvt.rn.f16x2.f32 %0, %1, %2;" : "=r"(r) : "f"(b), "f"(a));
    return r;
}

static __device__ __forceinline__ void mma_f16(float* c, uint32_t a0, uint32_t a1,
                                               uint32_t a2, uint32_t a3,
                                               uint32_t b0, uint32_t b1) {
    asm volatile(
        "mma.sync.aligned.m16n8k16.row.col.f32.f16.f16.f32 "
        "{%0,%1,%2,%3}, {%4,%5,%6,%7}, {%8,%9}, {%0,%1,%2,%3};"
        : "+f"(c[0]), "+f"(c[1]), "+f"(c[2]), "+f"(c[3])
        : "r"(a0), "r"(a1), "r"(a2), "r"(a3), "r"(b0), "r"(b1));
}

// one 32->32 GEMM on fragments: acc += fp16(x) @ (Whi + Wlo)
static __device__ __forceinline__ void gemm_frag(const char* smem,
                                                 const float x[2][4][4],
                                                 float acc[2][4][4],
                                                 int mbase, int lane)
{
    // build A-fragments (single fp16; no residual split)
    uint32_t ah[2][2][4];
    #pragma unroll
    for (int m = 0; m < 2; ++m) {
        #pragma unroll
        for (int kt = 0; kt < 2; ++kt) {
            #pragma unroll
            for (int r = 0; r < 4; ++r) {
                const float v0 = x[m][2 * kt + (r >> 1)][(r & 1) * 2 + 0];
                const float v1 = x[m][2 * kt + (r >> 1)][(r & 1) * 2 + 1];
                ah[m][kt][r] = cvt2h(v0, v1);
            }
        }
    }

    #pragma unroll
    for (int kt = 0; kt < 2; ++kt) {
        #pragma unroll
        for (int nt = 0; nt < 4; ++nt) {
            const int slot = ((kt * 4 + nt) * 32 + lane) * 16;
            uint4 v = *(const uint4*)(smem + mbase + slot);
            #pragma unroll
            for (int m = 0; m < 2; ++m) {
                mma_f16(acc[m][nt], ah[m][kt][0], ah[m][kt][1], ah[m][kt][2], ah[m][kt][3], v.x, v.y);
                mma_f16(acc[m][nt], ah[m][kt][0], ah[m][kt][1], ah[m][kt][2], ah[m][kt][3], v.z, v.w);
            }
        }
    }
}

__global__ void __launch_bounds__(TPB, 3)
decoder_sphere_mma(const float* __restrict__ p,
                   const float* __restrict__ c,
                   const float* __restrict__ fcpw,
                   const float* __restrict__ fcpb,
                   const float* __restrict__ w0g,
                   const float* __restrict__ b0g,
                   const float* __restrict__ w1g,
                   const float* __restrict__ b1g,
                   const float* __restrict__ fowg,
                   const float* __restrict__ fobg,
                   float* __restrict__ out)
{
    extern __shared__ __align__(16) char smem[];
    const int tid  = threadIdx.x;
    const int wid  = tid >> 5;
    const int lane = tid & 31;
    const int g    = lane >> 2;
    const int tig  = lane & 3;

    // ---- stage scalars ----
    for (int i = tid; i < 160; i += TPB) {
        *(float*)(smem + OFF_B0 + i * 4) = b0g[i];
        *(float*)(smem + OFF_B1 + i * 4) = b1g[i];
    }
    for (int i = tid; i < 96; i += TPB) *(float*)(smem + OFF_FCPW + i * 4) = fcpw[i];
    for (int i = tid; i < 32; i += TPB) *(float*)(smem + OFF_FCPB + i * 4) = fcpb[i];

    // ---- stage weights: fragment-ordered, fp16 hi/lo interleaved per 16B slot ----
    for (int idx = tid; idx < 5120; idx += TPB) {
        int l = idx >> 10;
        int r = idx & 1023;
        int k = r >> 5;     // input feature (K)
        int n = r & 31;     // output feature (N)
        int kt = k >> 4, kr = k & 15;
        int hb = kr >> 3, ktig = (kr >> 1) & 3, j = kr & 1;
        int gg = n & 7, nt = n >> 3;
        int ln = (gg << 2) | ktig;
        int slot = (((kt << 2) | nt) << 5) + ln;
        int bhi = slot * 16 + hb * 4 + j * 2;   // hi f16 byte offset
        int blo = bhi + 8;                       // lo f16 byte offset

        float v0 = w0g[idx];
        __half h0 = __float2half_rn(v0);
        __half l0 = __float2half_rn(v0 - __half2float(h0));
        *(__half*)(smem + MAT_BASE2(l, 0) + bhi) = h0;
        *(__half*)(smem + MAT_BASE2(l, 0) + blo) = l0;

        float v1 = w1g[idx];
        __half h1 = __float2half_rn(v1);
        __half l1 = __float2half_rn(v1 - __half2float(h1));
        *(__half*)(smem + MAT_BASE2(l, 1) + bhi) = h1;
        *(__half*)(smem + MAT_BASE2(l, 1) + blo) = l1;
    }

    // head weights (per-thread fragment) + bias
    float fwreg[8];
    #pragma unroll
    for (int nt = 0; nt < 4; ++nt) {
        fwreg[2 * nt]     = fowg[8 * nt + 2 * tig];
        fwreg[2 * nt + 1] = fowg[8 * nt + 2 * tig + 1];
    }
    const float fob = fobg[0];
    __syncthreads();

    // ---- persistent tile loop ----
    for (int t = blockIdx.x; t < NTILE; t += GRID) {
        const int tbase = t << 7;
        const int bb = tbase >> 16;              // batch constant per tile
        const int i = tbase + tid;

        // ---- phase 1: per-point indices/weights/p -> exchange ----
        {
            const float* pp = p + (size_t)i * 3;
            const float px = pp[0], py = pp[1], pz = pp[2];
            const float PI_F = 3.1415927410125732f;
            float lat = 90.0f - (atan2f(pz, sqrtf(px * px + py * py)) * 180.0f) / PI_F;
            float mer = fmodf(360.0f + (atan2f(py, px) * 180.0f) / PI_F, 360.0f);
            float y_grid = floorf(lat / 2.8125f);
            float x_grid = floorf(mer / 5.625f);
            float xlf = x_grid - 1.0f; xlf -= 64.0f * floorf(xlf * 0.015625f);
            float xrf = x_grid + 1.0f; xrf -= 64.0f * floorf(xrf * 0.015625f);
            float ylf = y_grid - 1.0f; ylf -= floorf(ylf * 0.015625f);
            float yhf = y_grid + 1.0f; yhf -= floorf(yhf * 0.015625f);
            const float dx = xrf - x_grid;
            const float dy = yhf - y_grid;
            const int xl = (int)xlf, xr = (int)xrf, yl = (int)ylf, yh = (int)yhf;

            char* ex = smem + OFF_EX + tid * EX_STRIDE;
            *(int4*)(ex) = make_int4((xl * 64 + yl) * 32, (xr * 64 + yl) * 32,
                                     (xl * 64 + yh) * 32, (xr * 64 + yh) * 32);
            *(float4*)(ex + 16) = make_float4(dx * dy, (1.0f - dx) * dy,
                                              dx * (1.0f - dy), (1.0f - dx) * (1.0f - dy));
            *(float4*)(ex + 32) = make_float4(px, py, pz, 0.0f);
        }
        __syncthreads();

        // ---- phase 2: cooperative coalesced gather -> BUFCF[point][col] ----
        {
            const float* gbase = c + (size_t)bb * (64 * 64 * 32);
            const int sub = lane >> 3, piece = lane & 7;
            #pragma unroll
            for (int grp = 0; grp < 8; ++grp) {
                const int lp = 32 * wid + grp * 4 + sub;       // CTA-local point
                const char* ex = smem + OFF_EX + lp * EX_STRIDE;
                const int4 offs = *(const int4*)(ex);
                const float4 ws = *(const float4*)(ex + 16);
                float4 a  = *(const float4*)(gbase + offs.x + piece * 4);
                float4 b4 = *(const float4*)(gbase + offs.y + piece * 4);
                float4 c4 = *(const float4*)(gbase + offs.z + piece * 4);
                float4 d4 = *(const float4*)(gbase + offs.w + piece * 4);
                float4 acc;
                acc.x = a.x * ws.x + b4.x * ws.y + c4.x * ws.z + d4.x * ws.w;
                acc.y = a.y * ws.x + b4.y * ws.y + c4.y * ws.z + d4.y * ws.w;
                acc.z = a.z * ws.x + b4.z * ws.y + c4.z * ws.z + d4.z * ws.w;
                acc.w = a.w * ws.x + b4.w * ws.y + c4.w * ws.z + d4.w * ws.w;
                *(float4*)(smem + OFF_BUFCF + (lp * BUF_STRIDE + piece * 4) * 4) = acc;
            }
        }
        __syncthreads();

        // ---- phase 3: load cf fragments; compute net0 in fragment layout ----
        float net[2][4][4], cf[2][4][4];
        {
            float4 prow[2][2];
            #pragma unroll
            for (int m = 0; m < 2; ++m)
                #pragma unroll
                for (int rh = 0; rh < 2; ++rh) {
                    const int row = 32 * wid + g + 16 * m + 8 * rh;
                    prow[m][rh] = *(const float4*)(smem + OFF_EX + row * EX_STRIDE + 32);
                }
            #pragma unroll
            for (int nt = 0; nt < 4; ++nt) {
                const int col = 8 * nt + 2 * tig;
                float2 f0 = *(const float2*)(smem + OFF_FCPW + col * 4);
                float2 f1 = *(const float2*)(smem + OFF_FCPW + (32 + col) * 4);
                float2 f2 = *(const float2*)(smem + OFF_FCPW + (64 + col) * 4);
                float2 fb = *(const float2*)(smem + OFF_FCPB + col * 4);
                #pragma unroll
                for (int m = 0; m < 2; ++m) {
                    #pragma unroll
                    for (int rh = 0; rh < 2; ++rh) {
                        float4 pv = prow[m][rh];
                        net[m][nt][2 * rh]     = pv.x * f0.x + pv.y * f1.x + pv.z * f2.x + fb.x;
                        net[m][nt][2 * rh + 1] = pv.x * f0.y + pv.y * f1.y + pv.z * f2.y + fb.y;
                    }
                    const int rlo = 32 * wid + g + 16 * m;
                    float2 cl = *(const float2*)(smem + OFF_BUFCF + (rlo * BUF_STRIDE + col) * 4);
                    float2 ch = *(const float2*)(smem + OFF_BUFCF + ((rlo + 8) * BUF_STRIDE + col) * 4);
                    cf[m][nt][0] = cl.x; cf[m][nt][1] = cl.y;
                    cf[m][nt][2] = ch.x; cf[m][nt][3] = ch.y;
                }
            }
        }
        __syncthreads();   // buffers free for next tile

        // ---- 5 resnet blocks, fragment-resident ----
        #pragma unroll 1
        for (int l = 0; l < 5; ++l) {
            float xr[2][4][4], h[2][4][4];
            #pragma unroll
            for (int m = 0; m < 2; ++m)
                #pragma unroll
                for (int nt = 0; nt < 4; ++nt)
                    #pragma unroll
                    for (int j = 0; j < 4; ++j) {
                        net[m][nt][j] += cf[m][nt][j];
                        xr[m][nt][j] = fmaxf(net[m][nt][j], 0.0f);
                    }

            #pragma unroll
            for (int nt = 0; nt < 4; ++nt) {
                float2 bp = *(const float2*)(smem + OFF_B0 + (l * 32 + 8 * nt + 2 * tig) * 4);
                h[0][nt][0] = bp.x; h[0][nt][1] = bp.y; h[0][nt][2] = bp.x; h[0][nt][3] = bp.y;
                h[1][nt][0] = bp.x; h[1][nt][1] = bp.y; h[1][nt][2] = bp.x; h[1][nt][3] = bp.y;
            }
            gemm_frag(smem, xr, h, MAT_BASE2(l, 0), lane);

            float d[2][4][4];
            #pragma unroll
            for (int m = 0; m < 2; ++m)
                #pragma unroll
                for (int nt = 0; nt < 4; ++nt)
                    #pragma unroll
                    for (int j = 0; j < 4; ++j)
                        xr[m][nt][j] = fmaxf(h[m][nt][j], 0.0f);
            #pragma unroll
            for (int nt = 0; nt < 4; ++nt) {
                float2 bp = *(const float2*)(smem + OFF_B1 + (l * 32 + 8 * nt + 2 * tig) * 4);
                d[0][nt][0] = bp.x; d[0][nt][1] = bp.y; d[0][nt][2] = bp.x; d[0][nt][3] = bp.y;
                d[1][nt][0] = bp.x; d[1][nt][1] = bp.y; d[1][nt][2] = bp.x; d[1][nt][3] = bp.y;
            }
            gemm_frag(smem, xr, d, MAT_BASE2(l, 1), lane);

            #pragma unroll
            for (int m = 0; m < 2; ++m)
                #pragma unroll
                for (int nt = 0; nt < 4; ++nt)
                    #pragma unroll
                    for (int j = 0; j < 4; ++j)
                        net[m][nt][j] += d[m][nt][j];
        }

        // ---- head + quad reduction ----
        float pr0 = 0.f, pr1 = 0.f, pr2 = 0.f, pr3 = 0.f;
        #pragma unroll
        for (int nt = 0; nt < 4; ++nt) {
            pr0 += fmaxf(net[0][nt][0], 0.f) * fwreg[2 * nt] + fmaxf(net[0][nt][1], 0.f) * fwreg[2 * nt + 1];
            pr1 += fmaxf(net[0][nt][2], 0.f) * fwreg[2 * nt] + fmaxf(net[0][nt][3], 0.f) * fwreg[2 * nt + 1];
            pr2 += fmaxf(net[1][nt][0], 0.f) * fwreg[2 * nt] + fmaxf(net[1][nt][1], 0.f) * fwreg[2 * nt + 1];
            pr3 += fmaxf(net[1][nt][2], 0.f) * fwreg[2 * nt] + fmaxf(net[1][nt][3], 0.f) * fwreg[2 * nt + 1];
        }
        #pragma unroll
        for (int s = 1; s <= 2; s <<= 1) {
            pr0 += __shfl_xor_sync(0xffffffffu, pr0, s);
            pr1 += __shfl_xor_sync(0xffffffffu, pr1, s);
            pr2 += __shfl_xor_sync(0xffffffffu, pr2, s);
            pr3 += __shfl_xor_sync(0xffffffffu, pr3, s);
        }
        if (tig == 0) {
            const int base = tbase + 32 * wid + g;
            out[base]      = pr0 + fob;
            out[base + 8]  = pr1 + fob;
            out[base + 16] = pr2 + fob;
            out[base + 24] = pr3 + fob;
        }
    }
}

extern "C" void kernel_launch(void* const* d_in, const int* in_sizes, int n_in,
                              void* d_out, int out_size)
{
    const float* p    = (const float*)d_in[0];
    const float* c    = (const float*)d_in[2];
    const float* fcpw = (const float*)d_in[4];
    const float* fcpb = (const float*)d_in[5];
    const float* w0   = (const float*)d_in[6];
    const float* b0   = (const float*)d_in[7];
    const float* w1   = (const float*)d_in[8];
    const float* b1   = (const float*)d_in[9];
    const float* fow  = (const float*)d_in[10];
    const float* fob  = (const float*)d_in[11];
    float* out = (float*)d_out;

    cudaFuncSetAttribute(decoder_sphere_mma,
                         cudaFuncAttributeMaxDynamicSharedMemorySize, SMEM_BYTES);
    decoder_sphere_mma<<<GRID, TPB, SMEM_BYTES>>>(
        p, c, fcpw, fcpb, w0, b0, w1, b1, fow, fob, out);
}